// round 1
// baseline (speedup 1.0000x reference)
#include <cuda_runtime.h>
#include <cstddef>

// GazeLSTM: B=16384, T=128 (derived at runtime).
// out[b][t] = chain dirs; out[b][half] = LSTM hidden at step half.
//
// Thread mapping: even blocks -> backward chain + fused LSTM (one thread per b),
// odd blocks -> forward chain (one thread per b). Depth-1 matrix prefetch,
// unroll-2, weights in registers.

__device__ __forceinline__ float sigf(float x) {
    // 1/(1+exp(-x)); inf-safe for |x| huge (exp->0 or inf).
    float e = __expf(-x);
    return __fdividef(1.0f, 1.0f + e);
}

__device__ __forceinline__ float tanh_fast(float x) {
    // tanh(x) = 1 - 2/(exp(2x)+1); inf-safe both directions.
    float e = __expf(2.0f * x);
    return 1.0f - __fdividef(2.0f, e + 1.0f);
}

__device__ __forceinline__ void ld9(float* m, const float* __restrict__ p) {
#pragma unroll
    for (int i = 0; i < 9; i++) m[i] = __ldg(p + i);
}

#define LSTM_STEP(x0, x1, x2)                                                       \
    do {                                                                            \
        float g_[12];                                                               \
        _Pragma("unroll") for (int gg = 0; gg < 12; gg++) {                         \
            g_[gg] = fmaf(wih[gg * 3 + 0], (x0),                                    \
                     fmaf(wih[gg * 3 + 1], (x1),                                    \
                     fmaf(wih[gg * 3 + 2], (x2),                                    \
                     fmaf(whh[gg * 3 + 0], h0,                                      \
                     fmaf(whh[gg * 3 + 1], h1,                                      \
                     fmaf(whh[gg * 3 + 2], h2, bias[gg]))))));                      \
        }                                                                           \
        float i0 = sigf(g_[0]),  i1 = sigf(g_[1]),  i2 = sigf(g_[2]);               \
        float f0 = sigf(g_[3]),  f1 = sigf(g_[4]),  f2 = sigf(g_[5]);               \
        float t0 = tanh_fast(g_[6]), t1 = tanh_fast(g_[7]), t2 = tanh_fast(g_[8]);  \
        float o0 = sigf(g_[9]),  o1 = sigf(g_[10]), o2 = sigf(g_[11]);              \
        c0 = fmaf(f0, c0, i0 * t0);                                                 \
        c1 = fmaf(f1, c1, i1 * t1);                                                 \
        c2 = fmaf(f2, c2, i2 * t2);                                                 \
        h0 = o0 * tanh_fast(c0);                                                    \
        h1 = o1 * tanh_fast(c1);                                                    \
        h2 = o2 * tanh_fast(c2);                                                    \
    } while (0)

__global__ __launch_bounds__(128) void gaze_lstm_kernel(
    const float* __restrict__ dir,   // [B,3]
    const float* __restrict__ R,     // [B,T,3,3]
    const float* __restrict__ Wih,   // [12,3]
    const float* __restrict__ Whh,   // [12,3]
    const float* __restrict__ bih,   // [12]
    const float* __restrict__ bhh,   // [12]
    float* __restrict__ out,         // [B,T,3]
    int B, int T)
{
    const int half = T >> 1;
    const int gb = blockIdx.x;
    const bool is_back = ((gb & 1) == 0);
    const int b = (gb >> 1) * 128 + threadIdx.x;
    if (b >= B) return;

    const float d0 = __ldg(dir + (size_t)b * 3 + 0);
    const float d1 = __ldg(dir + (size_t)b * 3 + 1);
    const float d2 = __ldg(dir + (size_t)b * 3 + 2);
    float v0 = d0, v1 = d1, v2 = d2;

    const float* Rb = R + (size_t)b * T * 9;
    float* ob = out + (size_t)b * T * 3;

    if (is_back) {
        // ---- backward chain (t = 0..half-1 uses R[half-1-t]^T) + fused LSTM ----
        float wih[36], whh[36], bias[12];
#pragma unroll
        for (int i = 0; i < 36; i++) { wih[i] = __ldg(Wih + i); whh[i] = __ldg(Whh + i); }
#pragma unroll
        for (int i = 0; i < 12; i++) bias[i] = __ldg(bih + i) + __ldg(bhh + i);

        float h0 = 0.f, h1 = 0.f, h2 = 0.f;
        float c0 = 0.f, c1 = 0.f, c2 = 0.f;

        float A[9];
        ld9(A, Rb + (size_t)(half - 1) * 9);

#pragma unroll 2
        for (int t = 0; t < half; t++) {
            // prefetch matrix for step t+1 (j = half-2-t), clamped to avoid branch
            int jn = half - 2 - t;
            jn = jn < 0 ? 0 : jn;
            float Nx[9];
            ld9(Nx, Rb + (size_t)jn * 9);

            // v = A^T v  (A row-major; transposed matvec)
            float n0 = fmaf(A[6], v2, fmaf(A[3], v1, A[0] * v0));
            float n1 = fmaf(A[7], v2, fmaf(A[4], v1, A[1] * v0));
            float n2 = fmaf(A[8], v2, fmaf(A[5], v1, A[2] * v0));
            v0 = n0; v1 = n1; v2 = n2;

            ob[t * 3 + 0] = v0;
            ob[t * 3 + 1] = v1;
            ob[t * 3 + 2] = v2;

            LSTM_STEP(v0, v1, v2);

#pragma unroll
            for (int i = 0; i < 9; i++) A[i] = Nx[i];
        }

        // step t = half consumes dir itself; h after this step is the output row
        LSTM_STEP(d0, d1, d2);
        ob[half * 3 + 0] = h0;
        ob[half * 3 + 1] = h1;
        ob[half * 3 + 2] = h2;
    } else {
        // ---- forward chain: t = half+1..T-1 uses R[t-1] (indices half..T-2) ----
        const float* p = Rb + (size_t)half * 9;
        float* of = ob + (size_t)(half + 1) * 3;
        const int n = T - 1 - half;  // 63 steps

        float A[9];
        ld9(A, p);

#pragma unroll 2
        for (int k = 0; k < n; k++) {
            int kn = k + 1 < n ? k + 1 : 0;
            float Nx[9];
            ld9(Nx, p + (size_t)kn * 9);

            // v = A v
            float n0 = fmaf(A[2], v2, fmaf(A[1], v1, A[0] * v0));
            float n1 = fmaf(A[5], v2, fmaf(A[4], v1, A[3] * v0));
            float n2 = fmaf(A[8], v2, fmaf(A[7], v1, A[6] * v0));
            v0 = n0; v1 = n1; v2 = n2;

            of[k * 3 + 0] = v0;
            of[k * 3 + 1] = v1;
            of[k * 3 + 2] = v2;

#pragma unroll
            for (int i = 0; i < 9; i++) A[i] = Nx[i];
        }
    }
}

extern "C" void kernel_launch(void* const* d_in, const int* in_sizes, int n_in,
                              void* d_out, int out_size)
{
    const float* dir = (const float*)d_in[0];
    const float* R   = (const float*)d_in[1];
    const float* Wih = (const float*)d_in[2];
    const float* Whh = (const float*)d_in[3];
    const float* bih = (const float*)d_in[4];
    const float* bhh = (const float*)d_in[5];
    float* out = (float*)d_out;

    const int B = in_sizes[0] / 3;
    const int T = in_sizes[1] / (B * 9);

    const int blocks_per_side = (B + 127) / 128;
    const int nblocks = blocks_per_side * 2;
    gaze_lstm_kernel<<<nblocks, 128>>>(dir, R, Wih, Whh, bih, bhh, out, B, T);
}

// round 2
// speedup vs baseline: 3.3969x; 3.3969x over previous
#include <cuda_runtime.h>
#include <cstddef>

// GazeLSTM on GB300. B=16384, T=128.
// Block = 64 threads = 64 batch elements, one direction per block
// (even blocks: backward chain + fused LSTM; odd: forward chain).
// R is staged into SMEM in chunks of C=4 matrices via cp.async (coalesced,
// double-buffered), stored transposed+swizzled for conflict-free LDS.
// Outputs staged in SMEM per chunk and written back coalesced.

#define BT 64          // threads (b's) per block
#define C  4           // matrices per chunk
#define CF (C * 9)     // 36 floats per b per chunk

__device__ __forceinline__ float tanhx(float x) {
    float y;
    asm("tanh.approx.f32 %0, %1;" : "=f"(y) : "f"(x));
    return y;
}
__device__ __forceinline__ float sigx(float x) {
    return fmaf(tanhx(0.5f * x), 0.5f, 0.5f);
}

#define CP4(dst_u32, src_ptr) \
    asm volatile("cp.async.ca.shared.global [%0], [%1], 4;" :: "r"(dst_u32), "l"(src_ptr))
#define CP_COMMIT() asm volatile("cp.async.commit_group;")
#define CP_WAIT1()  asm volatile("cp.async.wait_group 1;")
#define CP_WAIT0()  asm volatile("cp.async.wait_group 0;")

#define LSTM_STEP(x0, x1, x2)                                                       \
    do {                                                                            \
        float g_[12];                                                               \
        _Pragma("unroll") for (int gg = 0; gg < 12; gg++) {                         \
            g_[gg] = fmaf(wih[gg * 3 + 0], (x0),                                    \
                     fmaf(wih[gg * 3 + 1], (x1),                                    \
                     fmaf(wih[gg * 3 + 2], (x2),                                    \
                     fmaf(whh[gg * 3 + 0], h0,                                      \
                     fmaf(whh[gg * 3 + 1], h1,                                      \
                     fmaf(whh[gg * 3 + 2], h2, bias[gg]))))));                      \
        }                                                                           \
        float i0 = sigx(g_[0]),  i1 = sigx(g_[1]),  i2 = sigx(g_[2]);               \
        float f0 = sigx(g_[3]),  f1 = sigx(g_[4]),  f2 = sigx(g_[5]);               \
        float t0 = tanhx(g_[6]), t1 = tanhx(g_[7]), t2 = tanhx(g_[8]);              \
        float o0 = sigx(g_[9]),  o1 = sigx(g_[10]), o2 = sigx(g_[11]);              \
        c0 = fmaf(f0, c0, i0 * t0);                                                 \
        c1 = fmaf(f1, c1, i1 * t1);                                                 \
        c2 = fmaf(f2, c2, i2 * t2);                                                 \
        h0 = o0 * tanhx(c0);                                                        \
        h1 = o1 * tanhx(c1);                                                        \
        h2 = o2 * tanhx(c2);                                                        \
    } while (0)

// Cooperative coalesced store of NF floats/b from swizzled smem to gmem.
template <int NF>
__device__ __forceinline__ void store_chunk(float* __restrict__ gdst, size_t T3,
                                            const float* __restrict__ sout, int tid) {
#pragma unroll
    for (int k = 0; k < NF; k++) {
        int idx = k * BT + tid;
        int bp = idx / NF;
        int e = idx - bp * NF;
        gdst[(size_t)bp * T3 + e] = sout[e * BT + (bp ^ (e & 31))];
    }
}

// Stage one chunk: 64 b's x CF floats, gbase = R + bbase*T9 + j0*9.
__device__ __forceinline__ void stage_chunk(unsigned sbuf_u32,
                                            const float* __restrict__ gbase,
                                            int T9, int tid) {
    int bp = tid / CF;
    int e = tid - bp * CF;
#pragma unroll
    for (int k = 0; k < CF; k++) {
        const float* src = gbase + (size_t)bp * T9 + e;
        unsigned dst = sbuf_u32 + 4u * (unsigned)(e * BT + (bp ^ (e & 31)));
        CP4(dst, src);
        e += 28; bp += 1;               // advance by BT=64 = 1*36 + 28
        if (e >= CF) { e -= CF; bp += 1; }
    }
}

__global__ __launch_bounds__(BT) void gaze_lstm_kernel(
    const float* __restrict__ dir,   // [B,3]
    const float* __restrict__ R,     // [B,T,3,3]
    const float* __restrict__ Wih,   // [12,3]
    const float* __restrict__ Whh,   // [12,3]
    const float* __restrict__ bih,   // [12]
    const float* __restrict__ bhh,   // [12]
    float* __restrict__ out,         // [B,T,3]
    int B, int T)
{
    __shared__ float sbuf[2][CF * BT];   // 2 x 9216 B
    __shared__ float sout[(C * 3) * BT]; // 3072 B

    const int half = T >> 1;
    const int T9 = T * 9;
    const size_t T3 = (size_t)T * 3;
    const int tid = threadIdx.x;
    const int gb = blockIdx.x;
    const bool is_back = ((gb & 1) == 0);
    const int bbase = (gb >> 1) * BT;
    const int b = bbase + tid;

    const int nchunks = half / C;  // 16

    const float d0 = __ldg(dir + (size_t)b * 3 + 0);
    const float d1 = __ldg(dir + (size_t)b * 3 + 1);
    const float d2 = __ldg(dir + (size_t)b * 3 + 2);
    float v0 = d0, v1 = d1, v2 = d2;

    const float* Rblk = R + (size_t)bbase * T9;
    float* oblk = out + (size_t)bbase * T3;

    unsigned sb0 = (unsigned)__cvta_generic_to_shared(&sbuf[0][0]);
    unsigned sb1 = (unsigned)__cvta_generic_to_shared(&sbuf[1][0]);

    if (is_back) {
        // ---- backward chain: step t uses R[half-1-t]^T; chunk c loads
        //      matrices [half-C*(c+1), half-C*c), consumed in reverse ----
        float wih[36], whh[36], bias[12];
#pragma unroll
        for (int i = 0; i < 36; i++) { wih[i] = __ldg(Wih + i); whh[i] = __ldg(Whh + i); }
#pragma unroll
        for (int i = 0; i < 12; i++) bias[i] = __ldg(bih + i) + __ldg(bhh + i);

        float h0 = 0.f, h1 = 0.f, h2 = 0.f;
        float c0 = 0.f, c1 = 0.f, c2 = 0.f;

        // prologue: stage chunk 0
        stage_chunk(sb0, Rblk + (size_t)(half - C) * 9, T9, tid);
        CP_COMMIT();

        for (int cc = 0; cc < nchunks; cc++) {
            if (cc + 1 < nchunks) {
                int j0 = half - C * (cc + 2);
                stage_chunk((cc & 1) ? sb0 : sb1, Rblk + (size_t)j0 * 9, T9, tid);
                CP_COMMIT();
                CP_WAIT1();
            } else {
                CP_WAIT0();
            }
            __syncthreads();

            const float* buf = sbuf[cc & 1];
#pragma unroll
            for (int s = 0; s < C; s++) {
                const int e0 = (C - 1 - s) * 9;   // reverse order within chunk
                float A[9];
#pragma unroll
                for (int i = 0; i < 9; i++)
                    A[i] = buf[(e0 + i) * BT + (tid ^ ((e0 + i) & 31))];

                // v = A^T v
                float n0 = fmaf(A[6], v2, fmaf(A[3], v1, A[0] * v0));
                float n1 = fmaf(A[7], v2, fmaf(A[4], v1, A[1] * v0));
                float n2 = fmaf(A[8], v2, fmaf(A[5], v1, A[2] * v0));
                v0 = n0; v1 = n1; v2 = n2;

                const int eo = s * 3;
                sout[(eo + 0) * BT + (tid ^ ((eo + 0) & 31))] = v0;
                sout[(eo + 1) * BT + (tid ^ ((eo + 1) & 31))] = v1;
                sout[(eo + 2) * BT + (tid ^ ((eo + 2) & 31))] = v2;

                LSTM_STEP(v0, v1, v2);
            }
            __syncthreads();

            store_chunk<C * 3>(oblk + (size_t)(C * cc) * 3, T3, sout, tid);
        }

        // final LSTM step consumes dir; h is the output row at t=half
        LSTM_STEP(d0, d1, d2);
        float* ob = oblk + (size_t)tid * T3;
        ob[half * 3 + 0] = h0;
        ob[half * 3 + 1] = h1;
        ob[half * 3 + 2] = h2;
    } else {
        // ---- forward chain: step k (0..T-2-half) uses R[half+k],
        //      output row t = half+1+k ----
        const int nsteps = T - 1 - half;  // 63

        stage_chunk(sb0, Rblk + (size_t)half * 9, T9, tid);
        CP_COMMIT();

        for (int cc = 0; cc < nchunks; cc++) {
            if (cc + 1 < nchunks) {
                int j0 = half + C * (cc + 1);   // last chunk loads R[T-4..T-1]: in-bounds
                stage_chunk((cc & 1) ? sb0 : sb1, Rblk + (size_t)j0 * 9, T9, tid);
                CP_COMMIT();
                CP_WAIT1();
            } else {
                CP_WAIT0();
            }
            __syncthreads();

            const float* buf = sbuf[cc & 1];
            const int ns = (nsteps - C * cc) < C ? (nsteps - C * cc) : C;
#pragma unroll
            for (int s = 0; s < C; s++) {
                if (s < ns) {
                    const int e0 = s * 9;
                    float A[9];
#pragma unroll
                    for (int i = 0; i < 9; i++)
                        A[i] = buf[(e0 + i) * BT + (tid ^ ((e0 + i) & 31))];

                    // v = A v
                    float n0 = fmaf(A[2], v2, fmaf(A[1], v1, A[0] * v0));
                    float n1 = fmaf(A[5], v2, fmaf(A[4], v1, A[3] * v0));
                    float n2 = fmaf(A[8], v2, fmaf(A[7], v1, A[6] * v0));
                    v0 = n0; v1 = n1; v2 = n2;

                    const int eo = s * 3;
                    sout[(eo + 0) * BT + (tid ^ ((eo + 0) & 31))] = v0;
                    sout[(eo + 1) * BT + (tid ^ ((eo + 1) & 31))] = v1;
                    sout[(eo + 2) * BT + (tid ^ ((eo + 2) & 31))] = v2;
                }
            }
            __syncthreads();

            float* gdst = oblk + (size_t)(half + 1 + C * cc) * 3;
            if (ns == C) store_chunk<C * 3>(gdst, T3, sout, tid);
            else         store_chunk<9>(gdst, T3, sout, tid);   // last chunk: 3 steps
        }
    }
}

extern "C" void kernel_launch(void* const* d_in, const int* in_sizes, int n_in,
                              void* d_out, int out_size)
{
    const float* dir = (const float*)d_in[0];
    const float* R   = (const float*)d_in[1];
    const float* Wih = (const float*)d_in[2];
    const float* Whh = (const float*)d_in[3];
    const float* bih = (const float*)d_in[4];
    const float* bhh = (const float*)d_in[5];
    float* out = (float*)d_out;

    const int B = in_sizes[0] / 3;
    const int T = in_sizes[1] / (B * 9);

    const int nblocks = (B / BT) * 2;
    gaze_lstm_kernel<<<nblocks, BT>>>(dir, R, Wih, Whh, bih, bhh, out, B, T);
}

// round 3
// speedup vs baseline: 3.4598x; 1.0185x over previous
#include <cuda_runtime.h>
#include <cstddef>

// GazeLSTM on GB300 (sm_103a). B=16384, T=128.
// Block = 64 threads = 64 batch rows; even blocks: backward chain + fused LSTM,
// odd blocks: forward chain. R staged in chunks of C=8 matrices per b via
// 16B cp.async.cg (double-buffered), stored as [quad][b^swz] float4 for
// conflict-free LDS.128. LSTM gates computed with packed fma.rn.f32x2.

#define BT 64
#define C  8
#define NQ 18   // float4 per b per chunk (8 matrices * 9 floats = 72 f = 18 quads)

__device__ __forceinline__ unsigned long long pk2(float lo, float hi) {
    unsigned long long r; asm("mov.b64 %0, {%1, %2};" : "=l"(r) : "f"(lo), "f"(hi)); return r;
}
__device__ __forceinline__ void upk2(float& lo, float& hi, unsigned long long v) {
    asm("mov.b64 {%0, %1}, %2;" : "=f"(lo), "=f"(hi) : "l"(v));
}
__device__ __forceinline__ unsigned long long fma2(unsigned long long a, unsigned long long b, unsigned long long c) {
    unsigned long long d; asm("fma.rn.f32x2 %0, %1, %2, %3;" : "=l"(d) : "l"(a), "l"(b), "l"(c)); return d;
}
__device__ __forceinline__ unsigned long long mul2(unsigned long long a, unsigned long long b) {
    unsigned long long d; asm("mul.rn.f32x2 %0, %1, %2;" : "=l"(d) : "l"(a), "l"(b)); return d;
}
__device__ __forceinline__ float tanhx(float x) {
    float y; asm("tanh.approx.f32 %0, %1;" : "=f"(y) : "f"(x)); return y;
}

#define CP16(dst_u32, src_ptr) \
    asm volatile("cp.async.cg.shared.global [%0], [%1], 16;" :: "r"(dst_u32), "l"(src_ptr))
#define CP_COMMIT() asm volatile("cp.async.commit_group;")
#define CP_WAIT1()  asm volatile("cp.async.wait_group 1;")
#define CP_WAIT0()  asm volatile("cp.async.wait_group 0;")

// gates: pairs (0,1)(2,3)(4,5)=sigmoid(i,f)  (6,7)=tanh(g)  (8,9)=g8 tanh, o9 sig  (10,11)=sig
#define LSTM_STEP(x0, x1, x2)                                                        \
    do {                                                                             \
        unsigned long long xx0 = pk2((x0), (x0)), xx1 = pk2((x1), (x1)), xx2 = pk2((x2), (x2)); \
        unsigned long long hh0 = pk2(h0, h0), hh1 = pk2(h1, h1), hh2 = pk2(h2, h2);  \
        float th[12];                                                                \
        _Pragma("unroll") for (int p = 0; p < 6; p++) {                              \
            unsigned long long g =                                                   \
                fma2(WI[p][0], xx0, fma2(WI[p][1], xx1, fma2(WI[p][2], xx2,          \
                fma2(WH[p][0], hh0, fma2(WH[p][1], hh1, fma2(WH[p][2], hh2, BS[p])))))); \
            g = mul2(g, SC[p]);                                                      \
            float a_, b_; upk2(a_, b_, g);                                           \
            th[2 * p] = tanhx(a_); th[2 * p + 1] = tanhx(b_);                        \
        }                                                                            \
        float i0 = fmaf(0.5f, th[0], 0.5f), i1 = fmaf(0.5f, th[1], 0.5f), i2 = fmaf(0.5f, th[2], 0.5f); \
        float f0 = fmaf(0.5f, th[3], 0.5f), f1 = fmaf(0.5f, th[4], 0.5f), f2 = fmaf(0.5f, th[5], 0.5f); \
        float o0 = fmaf(0.5f, th[9], 0.5f), o1 = fmaf(0.5f, th[10], 0.5f), o2 = fmaf(0.5f, th[11], 0.5f); \
        c0 = fmaf(f0, c0, i0 * th[6]);                                               \
        c1 = fmaf(f1, c1, i1 * th[7]);                                               \
        c2 = fmaf(f2, c2, i2 * th[8]);                                               \
        h0 = o0 * tanhx(c0); h1 = o1 * tanhx(c1); h2 = o2 * tanhx(c2);               \
    } while (0)

// Stage one chunk: 64 b's x NQ float4, coalesced 16B cp.async.
// src4base = R (as float4) + bbase*t9q + (j0*9)/4 ; requires j0 % 4 == 0.
__device__ __forceinline__ void stage_chunk(float4* __restrict__ sdst,
                                            const float4* __restrict__ src4base,
                                            int t9q, int tid) {
    int bp = tid / NQ;
    int q  = tid - bp * NQ;
#pragma unroll
    for (int k = 0; k < NQ; k++) {
        const float4* src = src4base + (size_t)bp * t9q + q;
        unsigned dst = (unsigned)__cvta_generic_to_shared(sdst + q * BT + (bp ^ q));
        CP16(dst, src);
        bp += 3; q += 10;
        if (q >= NQ) { q -= NQ; bp += 1; }   // advance by 64 = 3*18 + 10
    }
}

// Load matrix M (compile-time index within chunk) for this thread's b.
template <int M>
__device__ __forceinline__ void loadA(float* A, const float4* __restrict__ buf, int tid) {
    constexpr int F0  = 9 * M;
    constexpr int QA  = F0 >> 2;
    constexpr int OFF = F0 & 3;
    float tmp[12];
    *(float4*)(tmp + 0) = buf[(QA + 0) * BT + (tid ^ (QA + 0))];
    *(float4*)(tmp + 4) = buf[(QA + 1) * BT + (tid ^ (QA + 1))];
    *(float4*)(tmp + 8) = buf[(QA + 2) * BT + (tid ^ (QA + 2))];
#pragma unroll
    for (int i = 0; i < 9; i++) A[i] = tmp[OFF + i];
}

// Coalesced writeback: NF floats per b, 64 b's, from swizzled sout.
template <int NF>
__device__ __forceinline__ void store_chunk(float* __restrict__ gdst, size_t T3,
                                            const float* __restrict__ sout, int tid) {
    int bp = tid / NF;
    int e  = tid - bp * NF;
    constexpr int DB = BT / NF;
    constexpr int DE = BT % NF;
#pragma unroll
    for (int k = 0; k < NF; k++) {
        gdst[(size_t)bp * T3 + e] = sout[e * BT + (bp ^ (e & 31))];
        bp += DB; e += DE;
        if (e >= NF) { e -= NF; bp += 1; }
    }
}

__global__ __launch_bounds__(BT) void gaze_lstm_kernel(
    const float* __restrict__ dir,   // [B,3]
    const float* __restrict__ R,     // [B,T,3,3]
    const float* __restrict__ Wih,   // [12,3]
    const float* __restrict__ Whh,   // [12,3]
    const float* __restrict__ bih,   // [12]
    const float* __restrict__ bhh,   // [12]
    float* __restrict__ out,         // [B,T,3]
    int B, int T)
{
    __shared__ float4 sbuf[2][NQ * BT];     // 2 x 18 KB
    __shared__ float  sout[(C * 3) * BT];   // 6 KB

    const int half = T >> 1;
    const int t9q = (T * 9) >> 2;           // float4 stride per b
    const size_t T3 = (size_t)T * 3;
    const int tid = threadIdx.x;
    const int gb = blockIdx.x;
    const bool is_back = ((gb & 1) == 0);
    const int bbase = (gb >> 1) * BT;
    const int b = bbase + tid;
    const int nchunks = half / C;           // 8

    const float d0 = __ldg(dir + (size_t)b * 3 + 0);
    const float d1 = __ldg(dir + (size_t)b * 3 + 1);
    const float d2 = __ldg(dir + (size_t)b * 3 + 2);
    float v0 = d0, v1 = d1, v2 = d2;

    const float4* R4blk = (const float4*)R + (size_t)bbase * t9q;
    float* oblk = out + (size_t)bbase * T3;

    if (is_back) {
        // weights, packed f32x2
        unsigned long long WI[6][3], WH[6][3], BS[6], SC[6];
#pragma unroll
        for (int p = 0; p < 6; p++) {
#pragma unroll
            for (int j = 0; j < 3; j++) {
                WI[p][j] = pk2(__ldg(Wih + (2 * p) * 3 + j), __ldg(Wih + (2 * p + 1) * 3 + j));
                WH[p][j] = pk2(__ldg(Whh + (2 * p) * 3 + j), __ldg(Whh + (2 * p + 1) * 3 + j));
            }
            BS[p] = pk2(__ldg(bih + 2 * p) + __ldg(bhh + 2 * p),
                        __ldg(bih + 2 * p + 1) + __ldg(bhh + 2 * p + 1));
        }
        SC[0] = pk2(0.5f, 0.5f); SC[1] = pk2(0.5f, 0.5f); SC[2] = pk2(0.5f, 0.5f);
        SC[3] = pk2(1.0f, 1.0f); SC[4] = pk2(1.0f, 0.5f); SC[5] = pk2(0.5f, 0.5f);

        float h0 = 0.f, h1 = 0.f, h2 = 0.f;
        float c0 = 0.f, c1 = 0.f, c2 = 0.f;

        // chunk cc holds matrices [half-8(cc+1), half-8cc), consumed in reverse
        stage_chunk(sbuf[0], R4blk + ((half - C) * 9 >> 2), t9q, tid);
        CP_COMMIT();

        for (int cc = 0; cc < nchunks; cc++) {
            if (cc + 1 < nchunks) {
                int j0 = half - C * (cc + 2);
                stage_chunk(sbuf[(cc + 1) & 1], R4blk + (j0 * 9 >> 2), t9q, tid);
                CP_COMMIT();
                CP_WAIT1();
            } else {
                CP_WAIT0();
            }
            __syncthreads();

            const float4* buf = sbuf[cc & 1];
#pragma unroll
            for (int s = 0; s < C; s++) {
                float A[9];
                switch (s) {   // matrix index 7-s, compile-time
                    case 0: loadA<7>(A, buf, tid); break;
                    case 1: loadA<6>(A, buf, tid); break;
                    case 2: loadA<5>(A, buf, tid); break;
                    case 3: loadA<4>(A, buf, tid); break;
                    case 4: loadA<3>(A, buf, tid); break;
                    case 5: loadA<2>(A, buf, tid); break;
                    case 6: loadA<1>(A, buf, tid); break;
                    default: loadA<0>(A, buf, tid); break;
                }
                // v = A^T v
                float n0 = fmaf(A[6], v2, fmaf(A[3], v1, A[0] * v0));
                float n1 = fmaf(A[7], v2, fmaf(A[4], v1, A[1] * v0));
                float n2 = fmaf(A[8], v2, fmaf(A[5], v1, A[2] * v0));
                v0 = n0; v1 = n1; v2 = n2;

                const int eo = s * 3;
                sout[(eo + 0) * BT + (tid ^ ((eo + 0) & 31))] = v0;
                sout[(eo + 1) * BT + (tid ^ ((eo + 1) & 31))] = v1;
                sout[(eo + 2) * BT + (tid ^ ((eo + 2) & 31))] = v2;

                LSTM_STEP(v0, v1, v2);
            }
            __syncthreads();

            store_chunk<C * 3>(oblk + (size_t)(C * cc) * 3, T3, sout, tid);
        }

        // final step consumes dir; h is the output row at t=half
        LSTM_STEP(d0, d1, d2);
        float* ob = oblk + (size_t)tid * T3;
        ob[half * 3 + 0] = h0;
        ob[half * 3 + 1] = h1;
        ob[half * 3 + 2] = h2;
    } else {
        // forward: step k uses R[half+k], writes row half+1+k, k = 0..T-2-half
        const int nsteps = T - 1 - half;  // 63

        stage_chunk(sbuf[0], R4blk + (half * 9 >> 2), t9q, tid);
        CP_COMMIT();

        for (int cc = 0; cc < nchunks; cc++) {
            if (cc + 1 < nchunks) {
                int j0 = half + C * (cc + 1);
                stage_chunk(sbuf[(cc + 1) & 1], R4blk + (j0 * 9 >> 2), t9q, tid);
                CP_COMMIT();
                CP_WAIT1();
            } else {
                CP_WAIT0();
            }
            __syncthreads();

            const float4* buf = sbuf[cc & 1];
            const int ns = (nsteps - C * cc) < C ? (nsteps - C * cc) : C;
#pragma unroll
            for (int s = 0; s < C; s++) {
                if (s < ns) {
                    float A[9];
                    switch (s) {
                        case 0: loadA<0>(A, buf, tid); break;
                        case 1: loadA<1>(A, buf, tid); break;
                        case 2: loadA<2>(A, buf, tid); break;
                        case 3: loadA<3>(A, buf, tid); break;
                        case 4: loadA<4>(A, buf, tid); break;
                        case 5: loadA<5>(A, buf, tid); break;
                        case 6: loadA<6>(A, buf, tid); break;
                        default: loadA<7>(A, buf, tid); break;
                    }
                    // v = A v
                    float n0 = fmaf(A[2], v2, fmaf(A[1], v1, A[0] * v0));
                    float n1 = fmaf(A[5], v2, fmaf(A[4], v1, A[3] * v0));
                    float n2 = fmaf(A[8], v2, fmaf(A[7], v1, A[6] * v0));
                    v0 = n0; v1 = n1; v2 = n2;

                    const int eo = s * 3;
                    sout[(eo + 0) * BT + (tid ^ ((eo + 0) & 31))] = v0;
                    sout[(eo + 1) * BT + (tid ^ ((eo + 1) & 31))] = v1;
                    sout[(eo + 2) * BT + (tid ^ ((eo + 2) & 31))] = v2;
                }
            }
            __syncthreads();

            float* gdst = oblk + (size_t)(half + 1 + C * cc) * 3;
            if (ns == C) store_chunk<C * 3>(gdst, T3, sout, tid);
            else         store_chunk<21>(gdst, T3, sout, tid);   // last chunk: 7 steps
        }
    }
}

extern "C" void kernel_launch(void* const* d_in, const int* in_sizes, int n_in,
                              void* d_out, int out_size)
{
    const float* dir = (const float*)d_in[0];
    const float* R   = (const float*)d_in[1];
    const float* Wih = (const float*)d_in[2];
    const float* Whh = (const float*)d_in[3];
    const float* bih = (const float*)d_in[4];
    const float* bhh = (const float*)d_in[5];
    float* out = (float*)d_out;

    const int B = in_sizes[0] / 3;
    const int T = in_sizes[1] / (B * 9);

    const int nblocks = (B / BT) * 2;
    gaze_lstm_kernel<<<nblocks, BT>>>(dir, R, Wih, Whh, bih, bhh, out, B, T);
}